// round 16
// baseline (speedup 1.0000x reference)
#include <cuda_runtime.h>
#include <cuda_fp16.h>
#include <math.h>
#include <math_constants.h>
#include <stdint.h>

// Problem constants
#define BQ 2
#define LQ 2048
#define DQ 1024
#define HQ 16
#define HDQ 64
#define MQ (BQ*LQ)          // 4096 rows
#define SSZ ((size_t)MQ*DQ)
#define GKF 2048            // K for both complex-cat GEMMs

// fp16 operands / intermediates
__device__ __half g_Ax[(size_t)MQ*GKF];        // [xr | xi]            16 MB
__device__ __half g_Bq[(size_t)6144*GKF];      // QKV weights cat      24 MB
__device__ __half g_QKVh[(size_t)MQ*6144];     // Q|K|V fp16 outputs   48 MB
__device__ __half g_Aoh[(size_t)MQ*GKF];       // [Or | Oi] (flash out)16 MB
__device__ __half g_Bo[(size_t)2048*GKF];      // O-proj weights cat    8 MB

// ---------------------------------------------------------------------------
// Prep kernels
// ---------------------------------------------------------------------------
__global__ void build_Ax(const float* __restrict__ xr, const float* __restrict__ xi,
                         __half* __restrict__ A)
{
    const int idx = blockIdx.x * blockDim.x + threadIdx.x;
    if (idx >= MQ*DQ) return;
    const int m = idx >> 10, k = idx & 1023;
    A[(size_t)m*GKF + k]        = __float2half(xr[idx]);
    A[(size_t)m*GKF + 1024 + k] = __float2half(xi[idx]);
}

// QKV B rows, per head: [Qr d0..63 | Qi d0..63] at h*128.
// Q scale folds 0.125 * log2(e) (flash uses exp2).
__global__ void build_Bqkv(const float* __restrict__ wr, const float* __restrict__ wi,
                           __half* __restrict__ B, int sec, float scale)
{
    const int idx = blockIdx.x * blockDim.x + threadIdx.x;
    if (idx >= DQ*DQ) return;
    const int o = idx >> 10, k = idx & 1023;
    const int h = o >> 6, d = o & 63;
    const float r = wr[idx] * scale, im = wi[idx] * scale;
    const size_t rowr = (size_t)(sec + h*128 + d) * GKF;
    const size_t rowi = (size_t)(sec + h*128 + 64 + d) * GKF;
    B[rowr + k]        = __float2half(r);
    B[rowr + 1024 + k] = __float2half(-im);
    B[rowi + k]        = __float2half(im);
    B[rowi + 1024 + k] = __float2half(r);
}

__global__ void build_Bo(const float* __restrict__ wr, const float* __restrict__ wi,
                         __half* __restrict__ B)
{
    const int idx = blockIdx.x * blockDim.x + threadIdx.x;
    if (idx >= DQ*DQ) return;
    const int o = idx >> 10, k = idx & 1023;
    const float r = wr[idx], im = wi[idx];
    const size_t rowr = (size_t)o * GKF;
    const size_t rowi = (size_t)(1024 + o) * GKF;
    B[rowr + k]        = __float2half(r);
    B[rowr + 1024 + k] = __float2half(-im);
    B[rowi + k]        = __float2half(im);
    B[rowi + 1024 + k] = __float2half(r);
}

// ---------------------------------------------------------------------------
// mma helpers
// ---------------------------------------------------------------------------
__device__ __forceinline__ void ldsm_x4(uint32_t& r0, uint32_t& r1,
                                        uint32_t& r2, uint32_t& r3, uint32_t addr)
{
    asm volatile("ldmatrix.sync.aligned.m8n8.x4.shared.b16 {%0,%1,%2,%3}, [%4];"
                 : "=r"(r0), "=r"(r1), "=r"(r2), "=r"(r3) : "r"(addr));
}

__device__ __forceinline__ void ldsm_x4t(uint32_t& r0, uint32_t& r1,
                                         uint32_t& r2, uint32_t& r3, uint32_t addr)
{
    asm volatile("ldmatrix.sync.aligned.m8n8.x4.trans.shared.b16 {%0,%1,%2,%3}, [%4];"
                 : "=r"(r0), "=r"(r1), "=r"(r2), "=r"(r3) : "r"(addr));
}

__device__ __forceinline__ void mma_f16(float* c,
                                        uint32_t a0, uint32_t a1, uint32_t a2, uint32_t a3,
                                        uint32_t b0, uint32_t b1)
{
    asm volatile("mma.sync.aligned.m16n8k16.row.col.f32.f16.f16.f32 "
                 "{%0,%1,%2,%3},{%4,%5,%6,%7},{%8,%9},{%0,%1,%2,%3};"
                 : "+f"(c[0]), "+f"(c[1]), "+f"(c[2]), "+f"(c[3])
                 : "r"(a0), "r"(a1), "r"(a2), "r"(a3), "r"(b0), "r"(b1));
}

__device__ __forceinline__ void cp_async16(uint32_t dst, const void* src)
{
    asm volatile("cp.async.cg.shared.global [%0], [%1], 16;"
                 :: "r"(dst), "l"(src));
}

// ---------------------------------------------------------------------------
// fp16 tensor-core GEMM (NT), K=2048, occ-2 (unchanged)
// ---------------------------------------------------------------------------
#define GBM 128
#define GBN 128
#define GBK 32
#define GLDA 40

template <int MODE>
__global__ __launch_bounds__(256, 2)
void gemmF(const __half* __restrict__ A, const __half* __restrict__ B,
           void* __restrict__ outv, int NS,
           const float* __restrict__ br, const float* __restrict__ bi)
{
    __shared__ __half smA[2][GBM*GLDA];
    __shared__ __half smB[2][GBN*GLDA];

    const int tid = threadIdx.x;
    const int m0 = blockIdx.y * GBM;
    const int n0 = blockIdx.x * GBN;
    const int w = tid >> 5, l = tid & 31;
    const int wm = (w & 1) * 64;
    const int wn = (w >> 1) * 32;
    const int g = l >> 2, t = l & 3;

    const int lr = tid >> 2;
    const int lk = (tid & 3) << 3;

    const __half* gA0 = A + (size_t)(m0 + lr) * GKF + lk;
    const __half* gA1 = gA0 + (size_t)64 * GKF;
    const __half* gB0 = B + (size_t)(n0 + lr) * GKF + lk;
    const __half* gB1 = gB0 + (size_t)64 * GKF;

    float acc[4][4][4];
    #pragma unroll
    for (int i = 0; i < 4; i++)
        #pragma unroll
        for (int j = 0; j < 4; j++)
            #pragma unroll
            for (int v = 0; v < 4; v++) acc[i][j][v] = 0.f;

    uint4 ra0 = *(const uint4*)gA0;
    uint4 ra1 = *(const uint4*)gA1;
    uint4 rb0 = *(const uint4*)gB0;
    uint4 rb1 = *(const uint4*)gB1;
    *(uint4*)&smA[0][lr*GLDA + lk]        = ra0;
    *(uint4*)&smA[0][(lr + 64)*GLDA + lk] = ra1;
    *(uint4*)&smB[0][lr*GLDA + lk]        = rb0;
    *(uint4*)&smB[0][(lr + 64)*GLDA + lk] = rb1;
    __syncthreads();

    const int aRow = wm + (l & 15);
    const int aK   = (l >> 4) << 3;
    const int bRow = wn + (l & 7) + (((l >> 4) & 1) << 3);
    const int bK   = ((l >> 3) & 1) << 3;

    const int NK = GKF / GBK;   // 64
    for (int kt = 0; kt < NK; kt++) {
        const int cur = kt & 1;
        if (kt + 1 < NK) {
            const size_t ko = (size_t)(kt + 1) * GBK;
            ra0 = *(const uint4*)(gA0 + ko);
            ra1 = *(const uint4*)(gA1 + ko);
            rb0 = *(const uint4*)(gB0 + ko);
            rb1 = *(const uint4*)(gB1 + ko);
        }
        const uint32_t aBase = (uint32_t)__cvta_generic_to_shared(&smA[cur][0]);
        const uint32_t bBase = (uint32_t)__cvta_generic_to_shared(&smB[cur][0]);
        #pragma unroll
        for (int ks = 0; ks < GBK; ks += 16) {
            uint32_t af[4][4], bfr[4][2];
            #pragma unroll
            for (int mt = 0; mt < 4; mt++) {
                const uint32_t ad = aBase +
                    (uint32_t)(((aRow + mt*16)*GLDA + ks + aK) * 2);
                ldsm_x4(af[mt][0], af[mt][1], af[mt][2], af[mt][3], ad);
            }
            #pragma unroll
            for (int np = 0; np < 2; np++) {
                const uint32_t bd = bBase +
                    (uint32_t)(((bRow + np*16)*GLDA + ks + bK) * 2);
                ldsm_x4(bfr[2*np][0], bfr[2*np][1], bfr[2*np+1][0], bfr[2*np+1][1], bd);
            }
            #pragma unroll
            for (int mt = 0; mt < 4; mt++)
                #pragma unroll
                for (int nt = 0; nt < 4; nt++)
                    mma_f16(acc[mt][nt],
                            af[mt][0], af[mt][1], af[mt][2], af[mt][3],
                            bfr[nt][0], bfr[nt][1]);
        }
        if (kt + 1 < NK) {
            const int nxt = cur ^ 1;
            *(uint4*)&smA[nxt][lr*GLDA + lk]        = ra0;
            *(uint4*)&smA[nxt][(lr + 64)*GLDA + lk] = ra1;
            *(uint4*)&smB[nxt][lr*GLDA + lk]        = rb0;
            *(uint4*)&smB[nxt][(lr + 64)*GLDA + lk] = rb1;
            __syncthreads();
        }
    }

    #pragma unroll
    for (int mt = 0; mt < 4; mt++) {
        const int row0 = m0 + wm + mt*16 + g;
        #pragma unroll
        for (int nt = 0; nt < 4; nt++) {
            const int c = n0 + wn + nt*8 + 2*t;
            if (MODE == 0) {
                __half* out = (__half*)outv;
                *(__half2*)&out[(size_t)row0 * NS + c] =
                    __floats2half2_rn(acc[mt][nt][0], acc[mt][nt][1]);
                *(__half2*)&out[(size_t)(row0 + 8) * NS + c] =
                    __floats2half2_rn(acc[mt][nt][2], acc[mt][nt][3]);
            } else {
                float* out = (float*)outv;
                const size_t cb = (size_t)(c >> 10) * SSZ + (c & 1023);
                const float* bp = (c & 1024) ? bi : br;
                const float b0 = bp[c & 1023];
                const float b1 = bp[(c & 1023) + 1];
                *(float2*)&out[cb + (size_t)row0 * 1024] =
                    make_float2(acc[mt][nt][0] + b0, acc[mt][nt][1] + b1);
                *(float2*)&out[cb + (size_t)(row0 + 8) * 1024] =
                    make_float2(acc[mt][nt][2] + b0, acc[mt][nt][3] + b1);
            }
        }
    }
}

// ---------------------------------------------------------------------------
// Flash attention, FA2-style register-P: 128 threads / 4 warps, warp w owns
// q-rows [w*16, w*16+16) x ALL 64 key cols. Score C-frags reused directly as
// PV A-frags (no P smem, 1 sync/iter). cp.async double-buffered K/V,
// trans-ldmatrix V, exp2 (log2e folded into Q weights).
// ---------------------------------------------------------------------------
#define LDK2 136    // K/V/Q row stride (128 + 8)
#define KVBUF (64*LDK2*2)   // bytes per K (or V) buffer = 17408
#define FL_SMEM (64*LDK2*2 + 2*KVBUF + 2*KVBUF)   // 87040 B

__global__ __launch_bounds__(128, 2)
void flash_mma(const __half* __restrict__ QKVh,
               __half* __restrict__ Aoh)
{
    extern __shared__ char smraw[];
    __half* Qs = (__half*)smraw;           // [64][LDK2]
    __half* Ks = Qs + 64*LDK2;             // [2][64][LDK2]
    __half* Vs = Ks + 2*64*LDK2;           // [2][64][LDK2]  (natural [k][d])

    const int qt = blockIdx.x, h = blockIdx.y, b = blockIdx.z;
    const int q0 = qt * 64;
    const int tid = threadIdx.x;
    const int w = tid >> 5, l = tid & 31;
    const int wm = w * 16;
    const int g = l >> 2, t4 = l & 3;

    // Q tile: 64 rows x 128 halves (scale*log2e pre-folded)
    // FIX R16: 8 x uint4 per thread (64 halves), was 4 in R15 -> half-garbage Q.
    {
        const int r = tid >> 1, cb = (tid & 1) * 64;
        const __half* src = QKVh + (size_t)(b*LQ + q0 + r)*6144 + h*128 + cb;
        __half* dst = Qs + r*LDK2 + cb;
        #pragma unroll
        for (int i = 0; i < 8; i++) ((uint4*)dst)[i] = ((const uint4*)src)[i];
    }

    // cp.async loader: thread owns one 128-B row-half for K and V
    const int lrr = tid >> 1, lcb = (tid & 1) * 64;
    const __half* gK = QKVh + (size_t)(b*LQ + lrr)*6144 + 2048 + h*128 + lcb;
    const __half* gV = gK + 2048;
    const uint32_t ksB = (uint32_t)__cvta_generic_to_shared(Ks);
    const uint32_t vsB = (uint32_t)__cvta_generic_to_shared(Vs);
    const uint32_t dK = ksB + (uint32_t)((lrr*LDK2 + lcb) * 2);
    const uint32_t dV = vsB + (uint32_t)((lrr*LDK2 + lcb) * 2);

    // prologue: tile 0 into buffer 0
    #pragma unroll
    for (int i = 0; i < 8; i++) {
        cp_async16(dK + i*16, gK + 8*i);
        cp_async16(dV + i*16, gV + 8*i);
    }
    asm volatile("cp.async.commit_group;");

    float lsum0 = 0.f, lsum1 = 0.f;
    float or_[8][4], oi_[8][4];
    #pragma unroll
    for (int nf = 0; nf < 8; nf++)
        #pragma unroll
        for (int v = 0; v < 4; v++) { or_[nf][v] = 0.f; oi_[nf][v] = 0.f; }

    const uint32_t qsB = (uint32_t)__cvta_generic_to_shared(Qs);

    const int aRow = wm + (l & 15);
    const int aK   = (l >> 4) << 3;
    const int bRowBase = (l & 7) + (((l >> 4) & 1) << 3);
    const int bK   = ((l >> 3) & 1) << 3;
    const int vRow = (l & 7) + (((l >> 3) & 1) << 3);
    const int vCol = (l >> 4) << 3;

    for (int kt = 0; kt <= qt; kt++) {
        const int k0 = kt * 64;
        asm volatile("cp.async.wait_group 0;" ::: "memory");
        __syncthreads();   // tile kt ready; prev iter fully consumed

        // issue tile kt+1 into the other buffer
        if (kt < qt) {
            const uint32_t off = ((kt + 1) & 1) * KVBUF;
            const __half* gKn = gK + (size_t)(kt + 1) * 64 * 6144;
            const __half* gVn = gV + (size_t)(kt + 1) * 64 * 6144;
            #pragma unroll
            for (int i = 0; i < 8; i++) {
                cp_async16(dK + off + i*16, gKn + 8*i);
                cp_async16(dV + off + i*16, gVn + 8*i);
            }
        }
        asm volatile("cp.async.commit_group;");

        const uint32_t kBase = ksB + (kt & 1) * KVBUF;
        const uint32_t vBase = vsB + (kt & 1) * KVBUF;

        // ---- scores: 16 q-rows x 64 cols per warp ----
        float s_[8][4];
        #pragma unroll
        for (int nf = 0; nf < 8; nf++)
            #pragma unroll
            for (int v = 0; v < 4; v++) s_[nf][v] = 0.f;

        #pragma unroll
        for (int ks = 0; ks < 128; ks += 16) {
            uint32_t a0, a1, a2, a3;
            ldsm_x4(a0, a1, a2, a3,
                    qsB + (uint32_t)((aRow*LDK2 + ks + aK) * 2));
            uint32_t bf_[8][2];
            #pragma unroll
            for (int np = 0; np < 4; np++) {
                ldsm_x4(bf_[2*np][0], bf_[2*np][1], bf_[2*np+1][0], bf_[2*np+1][1],
                        kBase + (uint32_t)(((bRowBase + 16*np)*LDK2 + ks + bK) * 2));
            }
            #pragma unroll
            for (int nf = 0; nf < 8; nf++)
                mma_f16(s_[nf], a0, a1, a2, a3, bf_[nf][0], bf_[nf][1]);
        }

        // ---- exp2 + mask + pack P into PV A-frags (registers only) ----
        const bool diag = (kt == qt);
        const int row0 = q0 + wm + g, row1 = row0 + 8;
        uint32_t pa[4][4];
        #pragma unroll
        for (int nf = 0; nf < 8; nf++) {
            const int c0 = k0 + nf*8 + t4*2;
            float p0 = exp2f(s_[nf][0]);
            float p1 = exp2f(s_[nf][1]);
            float p2 = exp2f(s_[nf][2]);
            float p3 = exp2f(s_[nf][3]);
            if (diag) {
                if (c0     > row0) p0 = 0.f;
                if (c0 + 1 > row0) p1 = 0.f;
                if (c0     > row1) p2 = 0.f;
                if (c0 + 1 > row1) p3 = 0.f;
            }
            lsum0 += p0 + p1;
            lsum1 += p2 + p3;
            const __half2 h01 = __floats2half2_rn(p0, p1);
            const __half2 h23 = __floats2half2_rn(p2, p3);
            pa[nf >> 1][(nf & 1)*2 + 0] = *(const uint32_t*)&h01;
            pa[nf >> 1][(nf & 1)*2 + 1] = *(const uint32_t*)&h23;
        }

        // ---- PV: A-frags from registers, V via ldmatrix.trans ----
        #pragma unroll
        for (int kk = 0; kk < 4; kk++) {
            const uint32_t vrow = (uint32_t)((kk*16 + vRow) * LDK2);
            uint32_t vr_[8][2], vi_[8][2];
            #pragma unroll
            for (int j = 0; j < 4; j++) {
                ldsm_x4t(vr_[2*j][0], vr_[2*j][1], vr_[2*j+1][0], vr_[2*j+1][1],
                         vBase + (uint32_t)((vrow + 16*j + vCol) * 2));
                ldsm_x4t(vi_[2*j][0], vi_[2*j][1], vi_[2*j+1][0], vi_[2*j+1][1],
                         vBase + (uint32_t)((vrow + 64 + 16*j + vCol) * 2));
            }
            #pragma unroll
            for (int nf = 0; nf < 8; nf++) {
                mma_f16(or_[nf], pa[kk][0], pa[kk][1], pa[kk][2], pa[kk][3],
                        vr_[nf][0], vr_[nf][1]);
                mma_f16(oi_[nf], pa[kk][0], pa[kk][1], pa[kk][2], pa[kk][3],
                        vi_[nf][0], vi_[nf][1]);
            }
        }
    }

    // epilogue: row sums complete within warp (4 threads per row)
    lsum0 += __shfl_xor_sync(0xffffffffu, lsum0, 1);
    lsum0 += __shfl_xor_sync(0xffffffffu, lsum0, 2);
    lsum1 += __shfl_xor_sync(0xffffffffu, lsum1, 1);
    lsum1 += __shfl_xor_sync(0xffffffffu, lsum1, 2);
    const float inv0 = 1.0f / lsum0;
    const float inv1 = 1.0f / lsum1;

    const int row0 = q0 + wm + g, row1 = row0 + 8;
    const size_t a0base = (size_t)(b*LQ + row0) * GKF + h*64;
    const size_t a1base = (size_t)(b*LQ + row1) * GKF + h*64;
    #pragma unroll
    for (int nf = 0; nf < 8; nf++) {
        const int c = nf*8 + t4*2;
        *(__half2*)&Aoh[a0base + c] =
            __floats2half2_rn(or_[nf][0]*inv0, or_[nf][1]*inv0);
        *(__half2*)&Aoh[a1base + c] =
            __floats2half2_rn(or_[nf][2]*inv1, or_[nf][3]*inv1);
        *(__half2*)&Aoh[a0base + 1024 + c] =
            __floats2half2_rn(oi_[nf][0]*inv0, oi_[nf][1]*inv0);
        *(__half2*)&Aoh[a1base + 1024 + c] =
            __floats2half2_rn(oi_[nf][2]*inv1, oi_[nf][3]*inv1);
    }
}

// ---------------------------------------------------------------------------
extern "C" void kernel_launch(void* const* d_in, const int* in_sizes, int n_in,
                              void* d_out, int out_size)
{
    const float* x_r  = (const float*)d_in[0];
    const float* x_i  = (const float*)d_in[1];
    const float* wq_r = (const float*)d_in[2];
    const float* wq_i = (const float*)d_in[3];
    const float* wk_r = (const float*)d_in[4];
    const float* wk_i = (const float*)d_in[5];
    const float* wv_r = (const float*)d_in[6];
    const float* wv_i = (const float*)d_in[7];
    const float* wo_r = (const float*)d_in[8];
    const float* wo_i = (const float*)d_in[9];
    const float* bo_r = (const float*)d_in[10];
    const float* bo_i = (const float*)d_in[11];

    __half *Ax, *Bq, *QKVh, *Aoh, *Bo;
    cudaGetSymbolAddress((void**)&Ax, g_Ax);
    cudaGetSymbolAddress((void**)&Bq, g_Bq);
    cudaGetSymbolAddress((void**)&QKVh, g_QKVh);
    cudaGetSymbolAddress((void**)&Aoh, g_Aoh);
    cudaGetSymbolAddress((void**)&Bo, g_Bo);

    float* yout = (float*)d_out;

    cudaFuncSetAttribute(flash_mma,
                         cudaFuncAttributeMaxDynamicSharedMemorySize, FL_SMEM);

    // ---- prep (0.125 * log2(e) folded into Q weights for exp2 softmax) ----
    build_Ax<<<(MQ*DQ)/256, 256>>>(x_r, x_i, Ax);
    build_Bqkv<<<(DQ*DQ)/256, 256>>>(wq_r, wq_i, Bq, 0, 0.125f * 1.44269504f);
    build_Bqkv<<<(DQ*DQ)/256, 256>>>(wk_r, wk_i, Bq, 2048, 1.0f);
    build_Bqkv<<<(DQ*DQ)/256, 256>>>(wv_r, wv_i, Bq, 4096, 1.0f);
    build_Bo<<<(DQ*DQ)/256, 256>>>(wo_r, wo_i, Bo);

    // ---- fused QKV complex GEMM ----
    dim3 gq(6144/GBN, MQ/GBM);
    gemmF<0><<<gq, 256>>>(Ax, Bq, QKVh, 6144, nullptr, nullptr);

    // ---- attention (register-P FA2 style) ----
    dim3 gf(LQ/64, HQ, BQ);
    flash_mma<<<gf, 128, FL_SMEM>>>(QKVh, Aoh);

    // ---- O projection + bias -> d_out ----
    dim3 go(2048/GBN, MQ/GBM);
    gemmF<1><<<go, 256>>>(Aoh, Bo, yout, 0, bo_r, bo_i);
}

// round 17
// speedup vs baseline: 1.0281x; 1.0281x over previous
#include <cuda_runtime.h>
#include <cuda_fp16.h>
#include <math.h>
#include <math_constants.h>
#include <stdint.h>

// Problem constants
#define BQ 2
#define LQ 2048
#define DQ 1024
#define HQ 16
#define HDQ 64
#define MQ (BQ*LQ)          // 4096 rows
#define SSZ ((size_t)MQ*DQ)
#define GKF 2048            // K for both complex-cat GEMMs

// fp16 operands / intermediates
__device__ __half g_Ax[(size_t)MQ*GKF];        // [xr | xi]            16 MB
__device__ __half g_Bq[(size_t)6144*GKF];      // QKV weights cat      24 MB
__device__ __half g_QKVh[(size_t)MQ*6144];     // Q|K|V fp16 outputs   48 MB
__device__ __half g_Aoh[(size_t)MQ*GKF];       // [Or | Oi] (flash out)16 MB
__device__ __half g_Bo[(size_t)2048*GKF];      // O-proj weights cat    8 MB

// ---------------------------------------------------------------------------
// Prep kernels
// ---------------------------------------------------------------------------
__global__ void build_Ax(const float* __restrict__ xr, const float* __restrict__ xi,
                         __half* __restrict__ A)
{
    const int idx = blockIdx.x * blockDim.x + threadIdx.x;
    if (idx >= MQ*DQ) return;
    const int m = idx >> 10, k = idx & 1023;
    A[(size_t)m*GKF + k]        = __float2half(xr[idx]);
    A[(size_t)m*GKF + 1024 + k] = __float2half(xi[idx]);
}

// QKV B rows, per head: [Qr d0..63 | Qi d0..63] at h*128. scale folds 0.125 into Q.
__global__ void build_Bqkv(const float* __restrict__ wr, const float* __restrict__ wi,
                           __half* __restrict__ B, int sec, float scale)
{
    const int idx = blockIdx.x * blockDim.x + threadIdx.x;
    if (idx >= DQ*DQ) return;
    const int o = idx >> 10, k = idx & 1023;
    const int h = o >> 6, d = o & 63;
    const float r = wr[idx] * scale, im = wi[idx] * scale;
    const size_t rowr = (size_t)(sec + h*128 + d) * GKF;
    const size_t rowi = (size_t)(sec + h*128 + 64 + d) * GKF;
    B[rowr + k]        = __float2half(r);
    B[rowr + 1024 + k] = __float2half(-im);
    B[rowi + k]        = __float2half(im);
    B[rowi + 1024 + k] = __float2half(r);
}

__global__ void build_Bo(const float* __restrict__ wr, const float* __restrict__ wi,
                         __half* __restrict__ B)
{
    const int idx = blockIdx.x * blockDim.x + threadIdx.x;
    if (idx >= DQ*DQ) return;
    const int o = idx >> 10, k = idx & 1023;
    const float r = wr[idx], im = wi[idx];
    const size_t rowr = (size_t)o * GKF;
    const size_t rowi = (size_t)(1024 + o) * GKF;
    B[rowr + k]        = __float2half(r);
    B[rowr + 1024 + k] = __float2half(-im);
    B[rowi + k]        = __float2half(im);
    B[rowi + 1024 + k] = __float2half(r);
}

// ---------------------------------------------------------------------------
// mma helpers
// ---------------------------------------------------------------------------
__device__ __forceinline__ void ldsm_x4(uint32_t& r0, uint32_t& r1,
                                        uint32_t& r2, uint32_t& r3, uint32_t addr)
{
    asm volatile("ldmatrix.sync.aligned.m8n8.x4.shared.b16 {%0,%1,%2,%3}, [%4];"
                 : "=r"(r0), "=r"(r1), "=r"(r2), "=r"(r3) : "r"(addr));
}

__device__ __forceinline__ void ldsm_x4t(uint32_t& r0, uint32_t& r1,
                                         uint32_t& r2, uint32_t& r3, uint32_t addr)
{
    asm volatile("ldmatrix.sync.aligned.m8n8.x4.trans.shared.b16 {%0,%1,%2,%3}, [%4];"
                 : "=r"(r0), "=r"(r1), "=r"(r2), "=r"(r3) : "r"(addr));
}

__device__ __forceinline__ void mma_f16(float* c,
                                        uint32_t a0, uint32_t a1, uint32_t a2, uint32_t a3,
                                        uint32_t b0, uint32_t b1)
{
    asm volatile("mma.sync.aligned.m16n8k16.row.col.f32.f16.f16.f32 "
                 "{%0,%1,%2,%3},{%4,%5,%6,%7},{%8,%9},{%0,%1,%2,%3};"
                 : "+f"(c[0]), "+f"(c[1]), "+f"(c[2]), "+f"(c[3])
                 : "r"(a0), "r"(a1), "r"(a2), "r"(a3), "r"(b0), "r"(b1));
}

__device__ __forceinline__ void cp_async16(uint32_t dst, const void* src)
{
    asm volatile("cp.async.cg.shared.global [%0], [%1], 16;"
                 :: "r"(dst), "l"(src));
}

// ---------------------------------------------------------------------------
// fp16 tensor-core GEMM (NT), K=2048, occ-2 (unchanged)
// ---------------------------------------------------------------------------
#define GBM 128
#define GBN 128
#define GBK 32
#define GLDA 40

template <int MODE>
__global__ __launch_bounds__(256, 2)
void gemmF(const __half* __restrict__ A, const __half* __restrict__ B,
           void* __restrict__ outv, int NS,
           const float* __restrict__ br, const float* __restrict__ bi)
{
    __shared__ __half smA[2][GBM*GLDA];
    __shared__ __half smB[2][GBN*GLDA];

    const int tid = threadIdx.x;
    const int m0 = blockIdx.y * GBM;
    const int n0 = blockIdx.x * GBN;
    const int w = tid >> 5, l = tid & 31;
    const int wm = (w & 1) * 64;
    const int wn = (w >> 1) * 32;
    const int g = l >> 2, t = l & 3;

    const int lr = tid >> 2;
    const int lk = (tid & 3) << 3;

    const __half* gA0 = A + (size_t)(m0 + lr) * GKF + lk;
    const __half* gA1 = gA0 + (size_t)64 * GKF;
    const __half* gB0 = B + (size_t)(n0 + lr) * GKF + lk;
    const __half* gB1 = gB0 + (size_t)64 * GKF;

    float acc[4][4][4];
    #pragma unroll
    for (int i = 0; i < 4; i++)
        #pragma unroll
        for (int j = 0; j < 4; j++)
            #pragma unroll
            for (int v = 0; v < 4; v++) acc[i][j][v] = 0.f;

    uint4 ra0 = *(const uint4*)gA0;
    uint4 ra1 = *(const uint4*)gA1;
    uint4 rb0 = *(const uint4*)gB0;
    uint4 rb1 = *(const uint4*)gB1;
    *(uint4*)&smA[0][lr*GLDA + lk]        = ra0;
    *(uint4*)&smA[0][(lr + 64)*GLDA + lk] = ra1;
    *(uint4*)&smB[0][lr*GLDA + lk]        = rb0;
    *(uint4*)&smB[0][(lr + 64)*GLDA + lk] = rb1;
    __syncthreads();

    const int aRow = wm + (l & 15);
    const int aK   = (l >> 4) << 3;
    const int bRow = wn + (l & 7) + (((l >> 4) & 1) << 3);
    const int bK   = ((l >> 3) & 1) << 3;

    const int NK = GKF / GBK;   // 64
    for (int kt = 0; kt < NK; kt++) {
        const int cur = kt & 1;
        if (kt + 1 < NK) {
            const size_t ko = (size_t)(kt + 1) * GBK;
            ra0 = *(const uint4*)(gA0 + ko);
            ra1 = *(const uint4*)(gA1 + ko);
            rb0 = *(const uint4*)(gB0 + ko);
            rb1 = *(const uint4*)(gB1 + ko);
        }
        const uint32_t aBase = (uint32_t)__cvta_generic_to_shared(&smA[cur][0]);
        const uint32_t bBase = (uint32_t)__cvta_generic_to_shared(&smB[cur][0]);
        #pragma unroll
        for (int ks = 0; ks < GBK; ks += 16) {
            uint32_t af[4][4], bfr[4][2];
            #pragma unroll
            for (int mt = 0; mt < 4; mt++) {
                const uint32_t ad = aBase +
                    (uint32_t)(((aRow + mt*16)*GLDA + ks + aK) * 2);
                ldsm_x4(af[mt][0], af[mt][1], af[mt][2], af[mt][3], ad);
            }
            #pragma unroll
            for (int np = 0; np < 2; np++) {
                const uint32_t bd = bBase +
                    (uint32_t)(((bRow + np*16)*GLDA + ks + bK) * 2);
                ldsm_x4(bfr[2*np][0], bfr[2*np][1], bfr[2*np+1][0], bfr[2*np+1][1], bd);
            }
            #pragma unroll
            for (int mt = 0; mt < 4; mt++)
                #pragma unroll
                for (int nt = 0; nt < 4; nt++)
                    mma_f16(acc[mt][nt],
                            af[mt][0], af[mt][1], af[mt][2], af[mt][3],
                            bfr[nt][0], bfr[nt][1]);
        }
        if (kt + 1 < NK) {
            const int nxt = cur ^ 1;
            *(uint4*)&smA[nxt][lr*GLDA + lk]        = ra0;
            *(uint4*)&smA[nxt][(lr + 64)*GLDA + lk] = ra1;
            *(uint4*)&smB[nxt][lr*GLDA + lk]        = rb0;
            *(uint4*)&smB[nxt][(lr + 64)*GLDA + lk] = rb1;
            __syncthreads();
        }
    }

    #pragma unroll
    for (int mt = 0; mt < 4; mt++) {
        const int row0 = m0 + wm + mt*16 + g;
        #pragma unroll
        for (int nt = 0; nt < 4; nt++) {
            const int c = n0 + wn + nt*8 + 2*t;
            if (MODE == 0) {
                __half* out = (__half*)outv;
                *(__half2*)&out[(size_t)row0 * NS + c] =
                    __floats2half2_rn(acc[mt][nt][0], acc[mt][nt][1]);
                *(__half2*)&out[(size_t)(row0 + 8) * NS + c] =
                    __floats2half2_rn(acc[mt][nt][2], acc[mt][nt][3]);
            } else {
                float* out = (float*)outv;
                const size_t cb = (size_t)(c >> 10) * SSZ + (c & 1023);
                const float* bp = (c & 1024) ? bi : br;
                const float b0 = bp[c & 1023];
                const float b1 = bp[(c & 1023) + 1];
                *(float2*)&out[cb + (size_t)row0 * 1024] =
                    make_float2(acc[mt][nt][0] + b0, acc[mt][nt][1] + b1);
                *(float2*)&out[cb + (size_t)(row0 + 8) * 1024] =
                    make_float2(acc[mt][nt][2] + b0, acc[mt][nt][3] + b1);
            }
        }
    }
}

// ---------------------------------------------------------------------------
// Flash attention (R14 design), with longest-processing-time-first scheduling:
// qt = gridDim.x-1-blockIdx.x so heavy causal CTAs launch first.
// 64-row q-tiles, occ-2, no online max, cp.async double-buffered K/V,
// V via ldmatrix.trans (no transpose prep).
// ---------------------------------------------------------------------------
#define LDK2 136    // K/V/Q row stride (128 + 8)
#define LDV 72      // P row stride (64 + 8)
#define KVBUF (64*LDK2*2)   // bytes per K (or V) buffer = 17408
#define FL_SMEM ((64*LDK2*5 + 64*LDV)*2 + 128*4)   // 96768 B

__global__ __launch_bounds__(256, 2)
void flash_mma(const __half* __restrict__ QKVh,
               __half* __restrict__ Aoh)
{
    extern __shared__ char smraw[];
    __half* Qs = (__half*)smraw;           // [64][LDK2]
    __half* Ks = Qs + 64*LDK2;             // [2][64][LDK2]
    __half* Vs = Ks + 2*64*LDK2;           // [2][64][LDK2]  (natural [k][d] layout)
    __half* Ph = Vs + 2*64*LDK2;           // [64][LDV]
    float* rsum = (float*)(Ph + 64*LDV);   // [2][64]

    // LPT scheduling: heaviest q-tiles first
    const int qt = gridDim.x - 1 - blockIdx.x;
    const int h = blockIdx.y, b = blockIdx.z;
    const int q0 = qt * 64;
    const int tid = threadIdx.x;
    const int w = tid >> 5, l = tid & 31;
    const int wm = (w & 3) * 16;
    const int wn = (w >> 2) * 32;
    const int g = l >> 2, t4 = l & 3;
    const int half_ = w >> 2;

    // Q tile (scale pre-folded into weights)
    {
        const int r = tid >> 2, cb = (tid & 3) * 32;
        const __half* src = QKVh + (size_t)(b*LQ + q0 + r)*6144 + h*128 + cb;
        __half* dst = Qs + r*LDK2 + cb;
        #pragma unroll
        for (int i = 0; i < 4; i++) ((uint4*)dst)[i] = ((const uint4*)src)[i];
    }

    // cp.async loader mapping: thread owns 64B of one row for K and V
    const int lrr = tid >> 2, lcb = (tid & 3) * 32;
    const __half* gK = QKVh + (size_t)(b*LQ + lrr)*6144 + 2048 + h*128 + lcb;
    const __half* gV = gK + 2048;
    const uint32_t ksB = (uint32_t)__cvta_generic_to_shared(Ks);
    const uint32_t vsB = (uint32_t)__cvta_generic_to_shared(Vs);
    const uint32_t dK = ksB + (uint32_t)((lrr*LDK2 + lcb) * 2);
    const uint32_t dV = vsB + (uint32_t)((lrr*LDK2 + lcb) * 2);

    // prologue: tile 0 into buffer 0
    #pragma unroll
    for (int i = 0; i < 4; i++) {
        cp_async16(dK + i*16, gK + 8*i);
        cp_async16(dV + i*16, gV + 8*i);
    }
    asm volatile("cp.async.commit_group;");

    float lsum0 = 0.f, lsum1 = 0.f;
    float or_[4][4], oi_[4][4];
    #pragma unroll
    for (int nf = 0; nf < 4; nf++)
        #pragma unroll
        for (int v = 0; v < 4; v++) { or_[nf][v] = 0.f; oi_[nf][v] = 0.f; }

    const uint32_t qsB = (uint32_t)__cvta_generic_to_shared(Qs);
    const uint32_t phB = (uint32_t)__cvta_generic_to_shared(Ph);

    const int aRow = wm + (l & 15);
    const int aK   = (l >> 4) << 3;
    const int bRow = wn + (l & 7) + (((l >> 4) & 1) << 3);
    const int bK   = ((l >> 3) & 1) << 3;
    const int pRow = wm + (l & 15);
    const int vRow = (l & 7) + (((l >> 3) & 1) << 3);
    const int vCol = (l >> 4) << 3;

    for (int kt = 0; kt <= qt; kt++) {
        const int k0 = kt * 64;
        asm volatile("cp.async.wait_group 0;" ::: "memory");
        __syncthreads();   // tile kt ready; prev iteration fully consumed

        // issue tile kt+1 into the other buffer (overlaps this tile's compute)
        if (kt < qt) {
            const uint32_t off = ((kt + 1) & 1) * KVBUF;
            const __half* gKn = gK + (size_t)(kt + 1) * 64 * 6144;
            const __half* gVn = gV + (size_t)(kt + 1) * 64 * 6144;
            #pragma unroll
            for (int i = 0; i < 4; i++) {
                cp_async16(dK + off + i*16, gKn + 8*i);
                cp_async16(dV + off + i*16, gVn + 8*i);
            }
        }
        asm volatile("cp.async.commit_group;");

        const uint32_t kBase = ksB + (kt & 1) * KVBUF;
        const uint32_t vBase = vsB + (kt & 1) * KVBUF;

        // ---- scores ----
        float s_[4][4];
        #pragma unroll
        for (int nf = 0; nf < 4; nf++)
            #pragma unroll
            for (int v = 0; v < 4; v++) s_[nf][v] = 0.f;

        #pragma unroll
        for (int ks = 0; ks < 128; ks += 16) {
            uint32_t a0, a1, a2, a3;
            ldsm_x4(a0, a1, a2, a3,
                    qsB + (uint32_t)((aRow*LDK2 + ks + aK) * 2));
            uint32_t bf_[4][2];
            #pragma unroll
            for (int np = 0; np < 2; np++) {
                ldsm_x4(bf_[2*np][0], bf_[2*np][1], bf_[2*np+1][0], bf_[2*np+1][1],
                        kBase + (uint32_t)(((bRow + 16*np)*LDK2 + ks + bK) * 2));
            }
            #pragma unroll
            for (int nf = 0; nf < 4; nf++)
                mma_f16(s_[nf], a0, a1, a2, a3, bf_[nf][0], bf_[nf][1]);
        }

        // ---- exp + mask + P write + partial row sums ----
        const bool diag = (kt == qt);
        const int row0 = q0 + wm + g, row1 = row0 + 8;
        #pragma unroll
        for (int nf = 0; nf < 4; nf++) {
            const int c0 = k0 + wn + nf*8 + t4*2;
            float p0 = __expf(s_[nf][0]);
            float p1 = __expf(s_[nf][1]);
            float p2 = __expf(s_[nf][2]);
            float p3 = __expf(s_[nf][3]);
            if (diag) {
                if (c0     > row0) p0 = 0.f;
                if (c0 + 1 > row0) p1 = 0.f;
                if (c0     > row1) p2 = 0.f;
                if (c0 + 1 > row1) p3 = 0.f;
            }
            lsum0 += p0 + p1;
            lsum1 += p2 + p3;
            const int c = wn + nf*8 + t4*2;
            *(__half2*)&Ph[(wm + g)*LDV + c]     = __floats2half2_rn(p0, p1);
            *(__half2*)&Ph[(wm + g + 8)*LDV + c] = __floats2half2_rn(p2, p3);
        }
        __syncthreads();   // P visible across warps

        // ---- PV: V via ldmatrix.trans from natural [k][d] layout ----
        #pragma unroll
        for (int ks = 0; ks < 64; ks += 16) {
            uint32_t a0, a1, a2, a3;
            ldsm_x4(a0, a1, a2, a3, phB + (uint32_t)((pRow*LDV + ks + aK) * 2));
            uint32_t vr_[4][2], vi_[4][2];
            ldsm_x4t(vr_[0][0], vr_[0][1], vr_[1][0], vr_[1][1],
                     vBase + (uint32_t)(((ks + vRow)*LDK2 + wn + vCol) * 2));
            ldsm_x4t(vr_[2][0], vr_[2][1], vr_[3][0], vr_[3][1],
                     vBase + (uint32_t)(((ks + vRow)*LDK2 + wn + 16 + vCol) * 2));
            ldsm_x4t(vi_[0][0], vi_[0][1], vi_[1][0], vi_[1][1],
                     vBase + (uint32_t)(((ks + vRow)*LDK2 + 64 + wn + vCol) * 2));
            ldsm_x4t(vi_[2][0], vi_[2][1], vi_[3][0], vi_[3][1],
                     vBase + (uint32_t)(((ks + vRow)*LDK2 + 64 + wn + 16 + vCol) * 2));
            #pragma unroll
            for (int nf = 0; nf < 4; nf++) {
                mma_f16(or_[nf], a0, a1, a2, a3, vr_[nf][0], vr_[nf][1]);
                mma_f16(oi_[nf], a0, a1, a2, a3, vi_[nf][0], vi_[nf][1]);
            }
        }
    }

    // epilogue: row-sum reduction, normalize, write fp16 Aoh cat
    lsum0 += __shfl_xor_sync(0xffffffffu, lsum0, 1);
    lsum0 += __shfl_xor_sync(0xffffffffu, lsum0, 2);
    lsum1 += __shfl_xor_sync(0xffffffffu, lsum1, 1);
    lsum1 += __shfl_xor_sync(0xffffffffu, lsum1, 2);
    if (t4 == 0) {
        rsum[half_*64 + wm + g]     = lsum0;
        rsum[half_*64 + wm + g + 8] = lsum1;
    }
    __syncthreads();
    const float inv0 = 1.0f / (rsum[wm + g]     + rsum[64 + wm + g]);
    const float inv1 = 1.0f / (rsum[wm + g + 8] + rsum[64 + wm + g + 8]);

    const int row0 = q0 + wm + g, row1 = row0 + 8;
    const size_t a0base = (size_t)(b*LQ + row0) * GKF + h*64;
    const size_t a1base = (size_t)(b*LQ + row1) * GKF + h*64;
    #pragma unroll
    for (int nf = 0; nf < 4; nf++) {
        const int c = wn + nf*8 + t4*2;
        *(__half2*)&Aoh[a0base + c] =
            __floats2half2_rn(or_[nf][0]*inv0, or_[nf][1]*inv0);
        *(__half2*)&Aoh[a1base + c] =
            __floats2half2_rn(or_[nf][2]*inv1, or_[nf][3]*inv1);
        *(__half2*)&Aoh[a0base + 1024 + c] =
            __floats2half2_rn(oi_[nf][0]*inv0, oi_[nf][1]*inv0);
        *(__half2*)&Aoh[a1base + 1024 + c] =
            __floats2half2_rn(oi_[nf][2]*inv1, oi_[nf][3]*inv1);
    }
}

// ---------------------------------------------------------------------------
extern "C" void kernel_launch(void* const* d_in, const int* in_sizes, int n_in,
                              void* d_out, int out_size)
{
    const float* x_r  = (const float*)d_in[0];
    const float* x_i  = (const float*)d_in[1];
    const float* wq_r = (const float*)d_in[2];
    const float* wq_i = (const float*)d_in[3];
    const float* wk_r = (const float*)d_in[4];
    const float* wk_i = (const float*)d_in[5];
    const float* wv_r = (const float*)d_in[6];
    const float* wv_i = (const float*)d_in[7];
    const float* wo_r = (const float*)d_in[8];
    const float* wo_i = (const float*)d_in[9];
    const float* bo_r = (const float*)d_in[10];
    const float* bo_i = (const float*)d_in[11];

    __half *Ax, *Bq, *QKVh, *Aoh, *Bo;
    cudaGetSymbolAddress((void**)&Ax, g_Ax);
    cudaGetSymbolAddress((void**)&Bq, g_Bq);
    cudaGetSymbolAddress((void**)&QKVh, g_QKVh);
    cudaGetSymbolAddress((void**)&Aoh, g_Aoh);
    cudaGetSymbolAddress((void**)&Bo, g_Bo);

    float* yout = (float*)d_out;

    cudaFuncSetAttribute(flash_mma,
                         cudaFuncAttributeMaxDynamicSharedMemorySize, FL_SMEM);

    // ---- prep (softmax scale folded into Q weights) ----
    build_Ax<<<(MQ*DQ)/256, 256>>>(x_r, x_i, Ax);
    build_Bqkv<<<(DQ*DQ)/256, 256>>>(wq_r, wq_i, Bq, 0, 0.125f);
    build_Bqkv<<<(DQ*DQ)/256, 256>>>(wk_r, wk_i, Bq, 2048, 1.0f);
    build_Bqkv<<<(DQ*DQ)/256, 256>>>(wv_r, wv_i, Bq, 4096, 1.0f);
    build_Bo<<<(DQ*DQ)/256, 256>>>(wo_r, wo_i, Bo);

    // ---- fused QKV complex GEMM ----
    dim3 gq(6144/GBN, MQ/GBM);
    gemmF<0><<<gq, 256>>>(Ax, Bq, QKVh, 6144, nullptr, nullptr);

    // ---- attention (reads Q/K/V straight from QKVh; LPT block order) ----
    dim3 gf(LQ/64, HQ, BQ);
    flash_mma<<<gf, 256, FL_SMEM>>>(QKVh, Aoh);

    // ---- O projection + bias -> d_out ----
    dim3 go(2048/GBN, MQ/GBM);
    gemmF<1><<<go, 256>>>(Aoh, Bo, yout, 0, bo_r, bo_i);
}